// round 1
// baseline (speedup 1.0000x reference)
#include <cuda_runtime.h>
#include <math.h>
#include <limits.h>

// WARP loss: per-row rejection sampling over pre-drawn negative candidates.
// input  [B,Y] f32, target [B,Y] f32 (one-hot), neg_candidates [B,T] i32.
// out[0] = sum_b  L_b * (1 - s_pos + s_neg)  where L_b = log((Y-1)/num_trials)
// for the first accepted candidate (1 + s_neg - s_pos >= 0), else 0.

__global__ void warp_loss_kernel(const float* __restrict__ input,
                                 const float* __restrict__ target,
                                 const int*   __restrict__ neg,
                                 float* __restrict__ out,
                                 int Y, int T) {
    const int row = blockIdx.x;
    const float* trow = target + (size_t)row * Y;
    const float* irow = input  + (size_t)row * Y;

    __shared__ int s_pos;    // index of the positive label
    __shared__ int s_first;  // first accepted trial index
    if (threadIdx.x == 0) { s_pos = -1; s_first = INT_MAX; }
    __syncthreads();

    // --- Phase 1: find positive index with early-exit chunked float4 scan ---
    // Y = 10000 is divisible by 4; handle a scalar tail anyway for safety.
    const int nvec = Y >> 2;
    const float4* tv = reinterpret_cast<const float4*>(trow);
    for (int base = 0; base < nvec; base += blockDim.x) {
        const int i = base + threadIdx.x;
        if (i < nvec) {
            float4 v = tv[i];
            if (v.x > 0.5f) s_pos = 4 * i;
            if (v.y > 0.5f) s_pos = 4 * i + 1;
            if (v.z > 0.5f) s_pos = 4 * i + 2;
            if (v.w > 0.5f) s_pos = 4 * i + 3;
        }
        __syncthreads();
        if (s_pos >= 0) break;   // uniform across block (shared flag)
    }
    if (s_pos < 0) {             // scalar tail (Y % 4 != 0) — not hit for Y=10000
        for (int i = (nvec << 2) + threadIdx.x; i < Y; i += blockDim.x)
            if (trow[i] > 0.5f) s_pos = i;
        __syncthreads();
    }

    const int pos = s_pos;
    const float sp = __ldg(&irow[pos]);   // broadcast load, same addr all threads

    // --- Phase 2: rejection sampling over T candidates (one thread each) ---
    if ((int)threadIdx.x < T) {
        const int c = neg[(size_t)row * T + threadIdx.x];
        const float sc = __ldg(&irow[c]);
        if (1.0f + sc - sp >= 0.0f) atomicMin(&s_first, (int)threadIdx.x);
    }
    __syncthreads();

    // --- Phase 3: loss for this row ---
    if (threadIdx.x == 0 && s_first != INT_MAX) {
        const int first = s_first;
        const int num_trials = first + 1;
        const int c = neg[(size_t)row * T + first];
        const float sn = __ldg(&irow[c]);            // L2 hit (just loaded)
        const float L = logf((float)((Y - 1) / num_trials));  // floor-div then log
        atomicAdd(out, L * (1.0f - sp + sn));
    }
}

extern "C" void kernel_launch(void* const* d_in, const int* in_sizes, int n_in,
                              void* d_out, int out_size) {
    const float* input  = (const float*)d_in[0];
    const float* target = (const float*)d_in[1];
    const int*   neg    = (const int*)d_in[2];
    float* out = (float*)d_out;

    const int Y = 10000;                 // fixed by problem spec
    const int B = in_sizes[0] / Y;       // 4096
    const int T = in_sizes[2] / B;       // 128

    cudaMemsetAsync(out, 0, (size_t)out_size * sizeof(float), 0);
    warp_loss_kernel<<<B, 256>>>(input, target, neg, out, Y, T);
}

// round 2
// speedup vs baseline: 1.0523x; 1.0523x over previous
#include <cuda_runtime.h>
#include <math.h>
#include <limits.h>

// WARP loss: per-row rejection sampling over pre-drawn negative candidates.
// input  [B,Y] f32, target [B,Y] f32 (one-hot), neg_candidates [B,T] i32.
// out[0] = sum_b  L_b * (1 - s_pos + s_neg)  where L_b = log((Y-1)/num_trials)
// for the first accepted candidate (1 + s_neg - s_pos >= 0), else 0.
//
// Strategy: one block per row.
//  - Candidate gathers issued FIRST (independent of pos) -> overlap with scan.
//  - Target scan in 8KB super-chunks (2 float4/thread), early exit via
//    __syncthreads_or (fused flag-reduce + barrier).

__global__ __launch_bounds__(256, 8)
void warp_loss_kernel(const float* __restrict__ input,
                      const float* __restrict__ target,
                      const int*   __restrict__ neg,
                      float* __restrict__ out,
                      int Y, int T) {
    const int row = blockIdx.x;
    const int tid = threadIdx.x;
    const float* irow = input  + (size_t)row * Y;
    const float* trow = target + (size_t)row * Y;

    __shared__ float sc_sh[128];
    __shared__ int   s_pos;
    __shared__ int   s_first;
    if (tid == 0) s_first = INT_MAX;

    // --- Phase 0: candidate gathers (independent of pos; overlaps the scan) ---
    float sc = 0.0f;
    if (tid < T) {
        const int c = __ldg(&neg[(size_t)row * T + tid]);
        sc = __ldg(&irow[c]);
        sc_sh[tid] = sc;
    }

    // --- Phase 1: find positive index; 8KB super-chunks, early exit ---
    const int nvec = Y >> 2;                       // Y=10000 -> 2500 float4
    const float4* tv = reinterpret_cast<const float4*>(trow);
    const float4 zero4 = make_float4(0.f, 0.f, 0.f, 0.f);

    bool done = false;
    for (int base = 0; base < nvec && !done; base += 512) {
        const int i0 = base + tid;
        const int i1 = base + 256 + tid;
        // both loads issued before any test -> 2 outstanding LDG.128/thread
        float4 a = (i0 < nvec) ? __ldg(&tv[i0]) : zero4;
        float4 b = (i1 < nvec) ? __ldg(&tv[i1]) : zero4;
        int found = 0;
        if (a.x != 0.0f) { s_pos = 4 * i0;     found = 1; }
        if (a.y != 0.0f) { s_pos = 4 * i0 + 1; found = 1; }
        if (a.z != 0.0f) { s_pos = 4 * i0 + 2; found = 1; }
        if (a.w != 0.0f) { s_pos = 4 * i0 + 3; found = 1; }
        if (b.x != 0.0f) { s_pos = 4 * i1;     found = 1; }
        if (b.y != 0.0f) { s_pos = 4 * i1 + 1; found = 1; }
        if (b.z != 0.0f) { s_pos = 4 * i1 + 2; found = 1; }
        if (b.w != 0.0f) { s_pos = 4 * i1 + 3; found = 1; }
        done = (__syncthreads_or(found) != 0);     // barrier orders s_pos write
    }
    // scalar tail for Y % 4 != 0 (not hit for Y=10000)
    if (!done) {
        int found = 0;
        for (int i = (nvec << 2) + tid; i < Y; i += blockDim.x)
            if (trow[i] != 0.0f) { s_pos = i; found = 1; }
        done = (__syncthreads_or(found) != 0);
    }

    const int pos = done ? s_pos : 0;
    const float sp = __ldg(&irow[pos]);            // broadcast (same addr)

    // --- Phase 2: first accepted trial ---
    if (tid < T) {
        if (1.0f + sc - sp >= 0.0f) atomicMin(&s_first, tid);
    }
    __syncthreads();

    // --- Phase 3: loss for this row ---
    if (tid == 0 && s_first != INT_MAX) {
        const int first = s_first;
        const int num_trials = first + 1;
        const float L = logf((float)((Y - 1) / num_trials));  // floor-div, then log
        atomicAdd(out, L * (1.0f - sp + sc_sh[first]));
    }
}

extern "C" void kernel_launch(void* const* d_in, const int* in_sizes, int n_in,
                              void* d_out, int out_size) {
    const float* input  = (const float*)d_in[0];
    const float* target = (const float*)d_in[1];
    const int*   neg    = (const int*)d_in[2];
    float* out = (float*)d_out;

    const int Y = 10000;                 // fixed by problem spec
    const int B = in_sizes[0] / Y;       // 4096
    const int T = in_sizes[2] / B;       // 128

    cudaMemsetAsync(out, 0, (size_t)out_size * sizeof(float), 0);
    warp_loss_kernel<<<B, 256>>>(input, target, neg, out, Y, T);
}

// round 3
// speedup vs baseline: 1.0585x; 1.0060x over previous
#include <cuda_runtime.h>
#include <math.h>
#include <limits.h>

// WARP loss: per-row rejection sampling over pre-drawn negative candidates.
// input  [B,Y] f32, target [B,Y] f32 (one-hot), neg_candidates [B,T] i32.
// out[0] = sum_b  L_b * (1 - s_pos + s_neg),  L_b = log((Y-1)/num_trials).
//
// R3: 128-thread blocks (16 CTAs/SM -> 2x independent early-exit streams),
// 4KB scan chunks (expected 21.6KB/row target read), warp-ballot first-trial
// reduction, finder-thread fetches s_pos score immediately.

__global__ __launch_bounds__(128, 16)
void warp_loss_kernel(const float* __restrict__ input,
                      const float* __restrict__ target,
                      const int*   __restrict__ neg,
                      float* __restrict__ out,
                      int Y, int T) {
    const int row = blockIdx.x;
    const int tid = threadIdx.x;
    const int lane = tid & 31;
    const int wid  = tid >> 5;
    const float* irow = input  + (size_t)row * Y;
    const float* trow = target + (size_t)row * Y;

    __shared__ float sc_sh[128];     // candidate scores
    __shared__ float s_pscore;       // score of positive label
    __shared__ int   s_first_w[4];   // per-warp first accepted trial

    // --- Phase 0: candidate gathers (independent of pos; overlap the scan) ---
    float sc = 0.0f;
    if (tid < T) {
        const int c = __ldg(&neg[(size_t)row * T + tid]);
        sc = __ldg(&irow[c]);
        sc_sh[tid] = sc;
    }

    // --- Phase 1: find positive; 4KB chunks (2 float4/thread), early exit ---
    const int nvec = Y >> 2;                        // Y=10000 -> 2500 float4
    const float4* tv = reinterpret_cast<const float4*>(trow);
    const float4 zero4 = make_float4(0.f, 0.f, 0.f, 0.f);

    bool done = false;
    for (int base = 0; base < nvec && !done; base += 256) {
        const int i0 = base + tid;
        const int i1 = base + 128 + tid;
        float4 a = (i0 < nvec) ? __ldg(&tv[i0]) : zero4;
        float4 b = (i1 < nvec) ? __ldg(&tv[i1]) : zero4;
        int p = -1;
        if (a.x != 0.0f) p = 4 * i0;
        if (a.y != 0.0f) p = 4 * i0 + 1;
        if (a.z != 0.0f) p = 4 * i0 + 2;
        if (a.w != 0.0f) p = 4 * i0 + 3;
        if (b.x != 0.0f) p = 4 * i1;
        if (b.y != 0.0f) p = 4 * i1 + 1;
        if (b.z != 0.0f) p = 4 * i1 + 2;
        if (b.w != 0.0f) p = 4 * i1 + 3;
        if (p >= 0) s_pscore = __ldg(&irow[p]);     // finder fetches score now
        done = (__syncthreads_or(p >= 0) != 0);
    }
    if (!done) {                                    // scalar tail (Y%4 != 0)
        int p = -1;
        for (int i = (nvec << 2) + tid; i < Y; i += blockDim.x)
            if (trow[i] != 0.0f) p = i;
        if (p >= 0) s_pscore = __ldg(&irow[p]);
        done = (__syncthreads_or(p >= 0) != 0);
        if (!done && tid == 0) s_pscore = irow[0];  // defensive fallback
        __syncthreads();
    }

    const float sp = s_pscore;

    // --- Phase 2: first accepted trial via warp ballot ---
    bool acc = (tid < T) && (1.0f + sc - sp >= 0.0f);
    unsigned m = __ballot_sync(0xFFFFFFFFu, acc);
    if (lane == 0) s_first_w[wid] = m ? (wid * 32 + __ffs(m) - 1) : INT_MAX;
    __syncthreads();

    // --- Phase 3: loss for this row ---
    if (tid == 0) {
        int first = s_first_w[0];
        first = min(first, s_first_w[1]);
        first = min(first, s_first_w[2]);
        first = min(first, s_first_w[3]);
        if (first != INT_MAX) {
            const int num_trials = first + 1;
            const float L = logf((float)((Y - 1) / num_trials));
            atomicAdd(out, L * (1.0f - sp + sc_sh[first]));
        }
    }
}

extern "C" void kernel_launch(void* const* d_in, const int* in_sizes, int n_in,
                              void* d_out, int out_size) {
    const float* input  = (const float*)d_in[0];
    const float* target = (const float*)d_in[1];
    const int*   neg    = (const int*)d_in[2];
    float* out = (float*)d_out;

    const int Y = 10000;                 // fixed by problem spec
    const int B = in_sizes[0] / Y;       // 4096
    const int T = in_sizes[2] / B;       // 128

    cudaMemsetAsync(out, 0, (size_t)out_size * sizeof(float), 0);
    warp_loss_kernel<<<B, 128>>>(input, target, neg, out, Y, T);
}